// round 12
// baseline (speedup 1.0000x reference)
#include <cuda_runtime.h>
#include <math_constants.h>

#define BB 512
#define NN 64
#define KKN 16
#define BN_ (BB*NN)      // 32768
#define BNK (BB*NN*KKN)  // 524288
#define EPSV 1e-5f

// ---------------- device scratch (static, no allocation) ----------------
__device__ float    d_h0[BN_*64];
__device__ float    d_h1[BN_*64];
__device__ float    d_h2[BN_*128];
__device__ float    d_h3[BN_*256];
__device__ int      d_idx[BB*NN*KKN];
__device__ float    d_H1[(size_t)BNK*256];   // edge tensor, layer a (max C1=256)
__device__ float    d_H2[(size_t)BNK*256];   // edge tensor, layer b
__device__ float    d_y[BN_*64];
__device__ unsigned d_scat[BN_*256];
__device__ float    d_part[1024*512];
__device__ float    d_sA[512], d_tA[512];    // FIX: classifier BN has C=512; was 256 -> overflow
__device__ float    d_sB[512], d_tB[512];
__device__ float    d_pool[BB*896];
__device__ float    d_z1p[BB*512], d_z1[BB*512];
__device__ float    d_z2p[BB*256], d_z2[BB*256];

#define ENC_NEG 0x007FFFFFu   // enc(-inf)

__device__ __forceinline__ unsigned encf(float f) {
    unsigned b = __float_as_uint(f);
    return (b & 0x80000000u) ? ~b : (b | 0x80000000u);
}
__device__ __forceinline__ float decf(unsigned u) {
    return (u & 0x80000000u) ? __uint_as_float(u ^ 0x80000000u) : __uint_as_float(~u);
}
__device__ __forceinline__ float lrelu(float v) { return v > 0.f ? v : 0.2f*v; }

// ---------------- input layer: y = x @ w_in ----------------
__global__ void k_ingemm(const float* __restrict__ x, const float* __restrict__ w,
                         float* __restrict__ y) {
    __shared__ float sw[6*64];
    __shared__ float sx[4][8];
    int tid = threadIdx.x;
    for (int i = tid; i < 384; i += 256) sw[i] = w[i];
    int row0 = blockIdx.x * 4;
    if (tid < 24) sx[tid/6][tid%6] = x[row0*6 + tid];
    __syncthreads();
    int r = tid >> 6, c = tid & 63;
    float s = 0.f;
#pragma unroll
    for (int k = 0; k < 6; k++) s += sx[r][k] * sw[k*64 + c];
    y[(size_t)(row0 + r)*64 + c] = s;
}

// ---------------- generic partial stats over row slabs ----------------
__global__ void k_statp(const float* __restrict__ A, float* __restrict__ part,
                        int C, int rowsPer) {
    int c = threadIdx.x;           // threads == C
    int b = blockIdx.x;
    float s = 0.f, q = 0.f;
    size_t r0 = (size_t)b * rowsPer;
    for (int r = 0; r < rowsPer; r++) {
        float v = A[(r0 + r)*C + c];
        s += v; q += v*v;
    }
    part[(size_t)b*2*C + c]     = s;
    part[(size_t)b*2*C + C + c] = q;
}

// ---------------- reduce partials -> bn scale/shift ----------------
__global__ void k_reduce_part(const float* __restrict__ part, int nPart, int C,
                              const float* __restrict__ g, const float* __restrict__ beta,
                              float* __restrict__ s_out, float* __restrict__ t_out,
                              float invCount) {
    int c = threadIdx.x;
    if (c >= C) return;
    float s = 0.f, q = 0.f;
    for (int p = 0; p < nPart; p++) {
        s += part[(size_t)p*2*C + c];
        q += part[(size_t)p*2*C + C + c];
    }
    float mean = s * invCount;
    float var  = q * invCount - mean*mean;
    float inv  = rsqrtf(var + EPSV);
    float sc   = g[c] * inv;
    s_out[c] = sc;
    t_out[c] = beta[c] - mean * sc;
}

// ---------------- single-block stats (classifier, M small) ----------------
__global__ void k_bnstat_rows(const float* __restrict__ A, int M, int C,
                              const float* __restrict__ g, const float* __restrict__ beta,
                              float* __restrict__ s_out, float* __restrict__ t_out) {
    int c = threadIdx.x;
    if (c >= C) return;
    float s = 0.f, q = 0.f;
    for (int r = 0; r < M; r++) {
        float v = A[(size_t)r*C + c];
        s += v; q += v*v;
    }
    float mean = s / (float)M;
    float var  = q / (float)M - mean*mean;
    float inv  = rsqrtf(var + EPSV);
    float sc   = g[c] * inv;
    s_out[c] = sc;
    t_out[c] = beta[c] - mean * sc;
}

// ---------------- apply bn + lrelu elementwise (in-place safe) ----------------
__global__ void k_apply(const float* __restrict__ y, const float* __restrict__ s,
                        const float* __restrict__ t, float* __restrict__ h,
                        size_t total, int Cmask) {
    size_t i = (size_t)blockIdx.x * blockDim.x + threadIdx.x;
    if (i >= total) return;
    int c = (int)(i & (size_t)Cmask);
    h[i] = lrelu(s[c]*y[i] + t[c]);
}

// ---------------- knn per batch (jax-faithful tie-break) ----------------
__global__ void k_knn(const float* __restrict__ X, int C, int* __restrict__ nidx) {
    __shared__ float sX[64][68];
    __shared__ float sG[64][65];
    __shared__ float ssq[64];
    int tid = threadIdx.x;
    int tx = tid & 15, ty = tid >> 4;
    int b = blockIdx.x;
    float acc[4][4] = {};
    for (int c0 = 0; c0 < C; c0 += 64) {
        for (int i = tid; i < 64*64; i += 256) {
            int n = i >> 6, c = i & 63;
            sX[n][c] = X[(size_t)(b*64 + n)*C + c0 + c];
        }
        __syncthreads();
#pragma unroll 8
        for (int k = 0; k < 64; k++) {
            float a[4], bb[4];
#pragma unroll
            for (int i = 0; i < 4; i++) a[i]  = sX[ty*4 + i][k];
#pragma unroll
            for (int j = 0; j < 4; j++) bb[j] = sX[tx*4 + j][k];
#pragma unroll
            for (int i = 0; i < 4; i++)
#pragma unroll
                for (int j = 0; j < 4; j++) acc[i][j] += a[i]*bb[j];
        }
        __syncthreads();
    }
#pragma unroll
    for (int i = 0; i < 4; i++)
#pragma unroll
        for (int j = 0; j < 4; j++) sG[ty*4 + i][tx*4 + j] = acc[i][j];
    __syncthreads();
    if (tid < 64) ssq[tid] = sG[tid][tid];
    __syncthreads();
    if (tid < 64) {
        int n = tid;
        float sqn = ssq[n];
        float dist[17]; int mi[17]; int cnt = 0;
        for (int m = 0; m < 64; m++) {
            float dm = (sqn - 2.f*sG[n][m]) + ssq[m];
            if (cnt < 17) {
                int p = cnt;
                while (p > 0 && dist[p-1] > dm) { dist[p] = dist[p-1]; mi[p] = mi[p-1]; p--; }
                dist[p] = dm; mi[p] = m; cnt++;
            } else if (dm < dist[16]) {
                int p = 16;
                while (p > 0 && dist[p-1] > dm) { dist[p] = dist[p-1]; mi[p] = mi[p-1]; p--; }
                dist[p] = dm; mi[p] = m;
            }
        }
        for (int j = 0; j < 16; j++) nidx[(b*64 + n)*16 + j] = mi[j + 1];
    }
}

// ---------------- brute-force edge layer a: H1raw = gather-feat @ W1 ----------------
// feat row r (= pt*16+kk): [ x[nb], x[pt]-x[nb] ]  (2C wide), W1 is (2C, C1)
__global__ void k_featgemm(const float* __restrict__ X, const float* __restrict__ W,
                           const int* __restrict__ nidx, float* __restrict__ H,
                           int C, int C1) {
    __shared__ float sF[16][68];
    __shared__ float sW[16][64];
    int tid = threadIdx.x;
    int tx = tid & 15, ty = tid >> 4;
    int r0 = blockIdx.y * 64, cg = blockIdx.x * 64;
    int twoC = 2*C;
    float acc[4][4] = {};
    for (int k0 = 0; k0 < twoC; k0 += 16) {
        for (int i = tid; i < 16*64; i += 256) {
            int k = i >> 6, n = i & 63;
            sW[k][n] = W[(size_t)(k0 + k)*C1 + cg + n];
        }
        for (int i = tid; i < 16*64; i += 256) {
            int k = i >> 6, rr = i & 63;
            int r = r0 + rr;
            int pt = r >> 4, kk = r & 15;
            int b = pt >> 6;
            int nbg = b*64 + nidx[pt*16 + kk];
            int col = k0 + k;
            float v;
            if (col < C) v = X[(size_t)nbg*C + col];
            else         v = X[(size_t)pt*C + (col - C)] - X[(size_t)nbg*C + (col - C)];
            sF[k][rr] = v;
        }
        __syncthreads();
#pragma unroll
        for (int k = 0; k < 16; k++) {
            float4 av = *(const float4*)&sF[k][ty*4];
            float4 bv = *(const float4*)&sW[k][tx*4];
            float a[4] = {av.x, av.y, av.z, av.w};
            float bb[4] = {bv.x, bv.y, bv.z, bv.w};
#pragma unroll
            for (int i = 0; i < 4; i++)
#pragma unroll
                for (int j = 0; j < 4; j++) acc[i][j] += a[i]*bb[j];
        }
        __syncthreads();
    }
#pragma unroll
    for (int i = 0; i < 4; i++) {
        float4 v = make_float4(acc[i][0], acc[i][1], acc[i][2], acc[i][3]);
        *(float4*)&H[(size_t)(r0 + ty*4 + i)*C1 + cg + tx*4] = v;
    }
}

// ---------------- generic tiled GEMM 64x64x16 ----------------
__global__ void k_gemm(const float* __restrict__ A, const float* __restrict__ Bm,
                       float* __restrict__ Cout, int M, int Kd, int Nd) {
    __shared__ float sA[16][68];
    __shared__ float sB[16][64];
    int tid = threadIdx.x;
    int tx = tid & 15, ty = tid >> 4;
    int m0 = blockIdx.y * 64, n0 = blockIdx.x * 64;
    float acc[4][4] = {};
    for (int k0 = 0; k0 < Kd; k0 += 16) {
        for (int i = tid; i < 64*16; i += 256) {
            int m = i >> 4, k = i & 15;
            sA[k][m] = A[(size_t)(m0 + m)*Kd + k0 + k];
        }
        for (int i = tid; i < 16*64; i += 256) {
            int k = i >> 6, n = i & 63;
            sB[k][n] = Bm[(size_t)(k0 + k)*Nd + n0 + n];
        }
        __syncthreads();
#pragma unroll
        for (int k = 0; k < 16; k++) {
            float4 av = *(const float4*)&sA[k][ty*4];
            float4 bv = *(const float4*)&sB[k][tx*4];
            float a[4] = {av.x, av.y, av.z, av.w};
            float bb[4] = {bv.x, bv.y, bv.z, bv.w};
#pragma unroll
            for (int i = 0; i < 4; i++)
#pragma unroll
                for (int j = 0; j < 4; j++) acc[i][j] += a[i]*bb[j];
        }
        __syncthreads();
    }
#pragma unroll
    for (int i = 0; i < 4; i++) {
        float4 v = make_float4(acc[i][0], acc[i][1], acc[i][2], acc[i][3]);
        *(float4*)&Cout[(size_t)(m0 + ty*4 + i)*Nd + n0 + tx*4] = v;
    }
}

// ---------------- scatter-max of post-activation H2 (per batch, per 64-ch group) ----------------
__global__ void k_scat(const float* __restrict__ H2, const int* __restrict__ nidx,
                       unsigned* __restrict__ scat, int C2) {
    __shared__ unsigned sS[64][64];
    __shared__ int sIdx[1024];
    int tid = threadIdx.x;
    int b = blockIdx.y, cg = blockIdx.x * 64;
    for (int i = tid; i < 4096; i += 256) sS[i >> 6][i & 63] = ENC_NEG;
    for (int i = tid; i < 1024; i += 256) sIdx[i] = nidx[b*1024 + i];
    __syncthreads();
    for (int i = tid; i < 1024*64; i += 256) {
        int e = i >> 6, c = i & 63;
        float v = H2[(size_t)(b*1024 + e)*C2 + cg + c];
        atomicMax(&sS[sIdx[e]][c], encf(v));
    }
    __syncthreads();
    for (int i = tid; i < 4096; i += 256) {
        int n = i >> 6, c = i & 63;
        scat[(size_t)(b*64 + n)*C2 + cg + c] = sS[n][c];
    }
}

// ---------------- -inf -> 0, decode ----------------
__global__ void k_where(const unsigned* __restrict__ scat, float* __restrict__ h,
                        size_t total) {
    size_t i = (size_t)blockIdx.x * blockDim.x + threadIdx.x;
    if (i >= total) return;
    unsigned u = scat[i];
    h[i] = (u == ENC_NEG) ? 0.f : decf(u);
}

// ---------------- global pooling: [mean_N | max_N] of concat(h1,h2,h3) ----------------
__global__ void k_pool(const float* __restrict__ h1, const float* __restrict__ h2,
                       const float* __restrict__ h3, float* __restrict__ pool) {
    int b = blockIdx.x;
    for (int c = threadIdx.x; c < 448; c += blockDim.x) {
        const float* src; int C, off;
        if (c < 64)       { src = h1; C = 64;  off = c; }
        else if (c < 192) { src = h2; C = 128; off = c - 64; }
        else              { src = h3; C = 256; off = c - 192; }
        float s = 0.f, mx = -CUDART_INF_F;
        for (int n = 0; n < 64; n++) {
            float v = src[(size_t)(b*64 + n)*C + off];
            s += v; mx = fmaxf(mx, v);
        }
        pool[b*896 + c]       = s * (1.f/64.f);
        pool[b*896 + 448 + c] = mx;
    }
}

// ---------------- classifier head: out = z @ wc3 + bc3 ----------------
__global__ void k_head(const float* __restrict__ z, const float* __restrict__ w,
                       const float* __restrict__ bias, float* __restrict__ out) {
    int i = blockIdx.x * blockDim.x + threadIdx.x;
    if (i >= 1024) return;
    int r = i >> 1, c = i & 1;
    float s = 0.f;
    for (int k = 0; k < 256; k++) s += z[r*256 + k] * w[k*2 + c];
    out[i] = s + bias[c];
}

// ---------------- host orchestration: brute-force faithful edge conv ----------------
static void run_edge(const float* X, int C, int C1, int C2,
                     const float* wA, const float* gA, const float* bA,
                     const float* wB, const float* gB, const float* bB,
                     float* hout,
                     int* idxp, float* H1p, float* H2p, float* partp,
                     unsigned* scatp, float* sAp, float* tAp, float* sBp, float* tBp) {
    k_knn<<<BB, 256>>>(X, C, idxp);
    dim3 g1(C1/64, BNK/64);
    k_featgemm<<<g1, 256>>>(X, wA, idxp, H1p, C, C1);
    k_statp<<<1024, C1>>>(H1p, partp, C1, BNK/1024);
    k_reduce_part<<<1, C1>>>(partp, 1024, C1, gA, bA, sAp, tAp, 1.0f/(float)BNK);
    k_apply<<<(unsigned)(((size_t)BNK*C1 + 255)/256), 256>>>(H1p, sAp, tAp, H1p, (size_t)BNK*C1, C1 - 1);
    dim3 g2(C2/64, BNK/64);
    k_gemm<<<g2, 256>>>(H1p, wB, H2p, BNK, C1, C2);
    k_statp<<<1024, C2>>>(H2p, partp, C2, BNK/1024);
    k_reduce_part<<<1, C2>>>(partp, 1024, C2, gB, bB, sBp, tBp, 1.0f/(float)BNK);
    k_apply<<<(unsigned)(((size_t)BNK*C2 + 255)/256), 256>>>(H2p, sBp, tBp, H2p, (size_t)BNK*C2, C2 - 1);
    dim3 gs(C2/64, BB);
    k_scat<<<gs, 256>>>(H2p, idxp, scatp, C2);
    k_where<<<(unsigned)(((size_t)BN_*C2 + 255)/256), 256>>>(scatp, hout, (size_t)BN_*C2);
}

extern "C" void kernel_launch(void* const* d_in, const int* in_sizes, int n_in,
                              void* d_out, int out_size) {
    // --- runtime input-order dispatch ---
    const float *x, *w_in, *g_in, *b_in;
    const float *w1a, *g1a, *b1a, *w1b, *g1b, *b1b;
    const float *w2a, *g2a, *b2a, *w2b, *g2b, *b2b;
    const float *w3a, *g3a, *b3a, *w3b, *g3b, *b3b;
    const float *wc1, *gc1, *bc1, *wc2, *gc2, *bc2, *wc3, *bc3;

    bool alpha = (n_in == 31 && in_sizes[0] == 64 && in_sizes[7] == 32768 &&
                  in_sizes[27] == 458752 && in_sizes[30] == 196608);
    if (alpha) {
        b1a = (const float*)d_in[0];  b1b = (const float*)d_in[1];
        b2a = (const float*)d_in[2];  b2b = (const float*)d_in[3];
        b3a = (const float*)d_in[4];  b3b = (const float*)d_in[5];
        b_in = (const float*)d_in[6];
        bc1 = (const float*)d_in[8];  bc2 = (const float*)d_in[9];  bc3 = (const float*)d_in[10];
        g1a = (const float*)d_in[11]; g1b = (const float*)d_in[12];
        g2a = (const float*)d_in[13]; g2b = (const float*)d_in[14];
        g3a = (const float*)d_in[15]; g3b = (const float*)d_in[16];
        g_in = (const float*)d_in[17];
        gc1 = (const float*)d_in[18]; gc2 = (const float*)d_in[19];
        w1a = (const float*)d_in[20]; w1b = (const float*)d_in[21];
        w2a = (const float*)d_in[22]; w2b = (const float*)d_in[23];
        w3a = (const float*)d_in[24]; w3b = (const float*)d_in[25];
        w_in = (const float*)d_in[26];
        wc1 = (const float*)d_in[27]; wc2 = (const float*)d_in[28]; wc3 = (const float*)d_in[29];
        x   = (const float*)d_in[30];
    } else {
        x    = (const float*)d_in[0];
        w_in = (const float*)d_in[2];
        g_in = (const float*)d_in[3];  b_in = (const float*)d_in[4];
        w1a = (const float*)d_in[5];  g1a = (const float*)d_in[6];  b1a = (const float*)d_in[7];
        w1b = (const float*)d_in[8];  g1b = (const float*)d_in[9];  b1b = (const float*)d_in[10];
        w2a = (const float*)d_in[11]; g2a = (const float*)d_in[12]; b2a = (const float*)d_in[13];
        w2b = (const float*)d_in[14]; g2b = (const float*)d_in[15]; b2b = (const float*)d_in[16];
        w3a = (const float*)d_in[17]; g3a = (const float*)d_in[18]; b3a = (const float*)d_in[19];
        w3b = (const float*)d_in[20]; g3b = (const float*)d_in[21]; b3b = (const float*)d_in[22];
        wc1 = (const float*)d_in[23]; gc1 = (const float*)d_in[24]; bc1 = (const float*)d_in[25];
        wc2 = (const float*)d_in[26]; gc2 = (const float*)d_in[27]; bc2 = (const float*)d_in[28];
        wc3 = (const float*)d_in[29]; bc3 = (const float*)d_in[30];
    }
    float* out = (float*)d_out;

    float *h0, *h1, *h2, *h3, *H1, *H2, *y, *part, *sA, *tA, *sB, *tB, *pool, *z1p, *z1, *z2p, *z2;
    int* idxp;
    unsigned* scat;
    cudaGetSymbolAddress((void**)&h0,  d_h0);
    cudaGetSymbolAddress((void**)&h1,  d_h1);
    cudaGetSymbolAddress((void**)&h2,  d_h2);
    cudaGetSymbolAddress((void**)&h3,  d_h3);
    cudaGetSymbolAddress((void**)&idxp, d_idx);
    cudaGetSymbolAddress((void**)&H1,  d_H1);
    cudaGetSymbolAddress((void**)&H2,  d_H2);
    cudaGetSymbolAddress((void**)&y,   d_y);
    cudaGetSymbolAddress((void**)&scat, d_scat);
    cudaGetSymbolAddress((void**)&part, d_part);
    cudaGetSymbolAddress((void**)&sA,  d_sA);
    cudaGetSymbolAddress((void**)&tA,  d_tA);
    cudaGetSymbolAddress((void**)&sB,  d_sB);
    cudaGetSymbolAddress((void**)&tB,  d_tB);
    cudaGetSymbolAddress((void**)&pool, d_pool);
    cudaGetSymbolAddress((void**)&z1p, d_z1p);
    cudaGetSymbolAddress((void**)&z1,  d_z1);
    cudaGetSymbolAddress((void**)&z2p, d_z2p);
    cudaGetSymbolAddress((void**)&z2,  d_z2);

    // ---- input layer: h0 = lrelu(bn(x @ w_in)) ----
    k_ingemm<<<BN_/4, 256>>>(x, w_in, y);
    k_statp<<<128, 64>>>(y, part, 64, 256);
    k_reduce_part<<<1, 64>>>(part, 128, 64, g_in, b_in, sA, tA, 1.0f/(float)BN_);
    k_apply<<<(BN_*64 + 255)/256, 256>>>(y, sA, tA, h0, (size_t)BN_*64, 63);

    // ---- edge convs (brute-force faithful) ----
    run_edge(h0, 64, 64, 64,   w1a, g1a, b1a, w1b, g1b, b1b, h1, idxp, H1, H2, part, scat, sA, tA, sB, tB);
    run_edge(h1, 64, 128, 128, w2a, g2a, b2a, w2b, g2b, b2b, h2, idxp, H1, H2, part, scat, sA, tA, sB, tB);
    run_edge(h2, 128, 256, 256, w3a, g3a, b3a, w3b, g3b, b3b, h3, idxp, H1, H2, part, scat, sA, tA, sB, tB);

    // ---- pooling ----
    k_pool<<<BB, 256>>>(h1, h2, h3, pool);

    // ---- classifier ----
    {
        dim3 g(512/64, BB/64);
        k_gemm<<<g, 256>>>(pool, wc1, z1p, BB, 896, 512);
        k_bnstat_rows<<<1, 512>>>(z1p, BB, 512, gc1, bc1, sA, tA);   // sA/tA now 512 wide
        k_apply<<<(BB*512 + 255)/256, 256>>>(z1p, sA, tA, z1, (size_t)BB*512, 511);
    }
    {
        dim3 g(256/64, BB/64);
        k_gemm<<<g, 256>>>(z1, wc2, z2p, BB, 512, 256);
        k_bnstat_rows<<<1, 256>>>(z2p, BB, 256, gc2, bc2, sA, tA);
        k_apply<<<(BB*256 + 255)/256, 256>>>(z2p, sA, tA, z2, (size_t)BB*256, 255);
    }
    k_head<<<4, 256>>>(z2, wc3, bc3, out);
}

// round 13
// speedup vs baseline: 2.3477x; 2.3477x over previous
#include <cuda_runtime.h>
#include <math_constants.h>

#define BB 512
#define NN 64
#define KKN 16
#define BN_ (BB*NN)      // 32768
#define BNK (BB*NN*KKN)  // 524288
#define EPSV 1e-5f

// ---------------- device scratch (static, no allocation) ----------------
__device__ float    d_h0[BN_*64];
__device__ float    d_h1[BN_*64];
__device__ float    d_h2[BN_*128];
__device__ float    d_h3[BN_*256];
__device__ int      d_idx[BB*NN*KKN];
__device__ float    d_P[BN_*512];       // [Pc | Pn] per row, stride 2*C1 (max C1=256)
__device__ float    d_Wc[128*512];      // combined weight (C x 2C1)
__device__ float    d_y[BN_*64];
__device__ unsigned d_scat[BN_*256];
__device__ float    d_part[1024*512];
__device__ float    d_sA[512], d_tA[512];   // sized for classifier C=512 (root-cause fix)
__device__ float    d_sB[512], d_tB[512];
__device__ float    d_pool[BB*896];
__device__ float    d_z1p[BB*512], d_z1[BB*512];
__device__ float    d_z2p[BB*256], d_z2[BB*256];

#define ENC_NEG 0x007FFFFFu   // enc(-inf)

__device__ __forceinline__ unsigned encf(float f) {
    unsigned b = __float_as_uint(f);
    return (b & 0x80000000u) ? ~b : (b | 0x80000000u);
}
__device__ __forceinline__ float decf(unsigned u) {
    return (u & 0x80000000u) ? __uint_as_float(u ^ 0x80000000u) : __uint_as_float(~u);
}
__device__ __forceinline__ float lrelu(float v) { return v > 0.f ? v : 0.2f*v; }

// ---------------- input layer: y = x @ w_in ----------------
__global__ void k_ingemm(const float* __restrict__ x, const float* __restrict__ w,
                         float* __restrict__ y) {
    __shared__ float sw[6*64];
    __shared__ float sx[4][8];
    int tid = threadIdx.x;
    for (int i = tid; i < 384; i += 256) sw[i] = w[i];
    int row0 = blockIdx.x * 4;
    if (tid < 24) sx[tid/6][tid%6] = x[row0*6 + tid];
    __syncthreads();
    int r = tid >> 6, c = tid & 63;
    float s = 0.f;
#pragma unroll
    for (int k = 0; k < 6; k++) s += sx[r][k] * sw[k*64 + c];
    y[(size_t)(row0 + r)*64 + c] = s;
}

// ---------------- generic partial stats over row slabs ----------------
__global__ void k_statp(const float* __restrict__ A, float* __restrict__ part,
                        int C, int rowsPer) {
    int c = threadIdx.x;
    int b = blockIdx.x;
    float s = 0.f, q = 0.f;
    size_t r0 = (size_t)b * rowsPer;
    for (int r = 0; r < rowsPer; r++) {
        float v = A[(r0 + r)*C + c];
        s += v; q += v*v;
    }
    part[(size_t)b*2*C + c]     = s;
    part[(size_t)b*2*C + C + c] = q;
}

// ---------------- reduce partials -> bn scale/shift ----------------
__global__ void k_reduce_part(const float* __restrict__ part, int nPart, int C,
                              const float* __restrict__ g, const float* __restrict__ beta,
                              float* __restrict__ s_out, float* __restrict__ t_out,
                              float invCount) {
    int c = threadIdx.x;
    if (c >= C) return;
    float s = 0.f, q = 0.f;
    for (int p = 0; p < nPart; p++) {
        s += part[(size_t)p*2*C + c];
        q += part[(size_t)p*2*C + C + c];
    }
    float mean = s * invCount;
    float var  = q * invCount - mean*mean;
    float inv  = rsqrtf(var + EPSV);
    float sc   = g[c] * inv;
    s_out[c] = sc;
    t_out[c] = beta[c] - mean * sc;
}

// ---------------- single-block stats (classifier) ----------------
__global__ void k_bnstat_rows(const float* __restrict__ A, int M, int C,
                              const float* __restrict__ g, const float* __restrict__ beta,
                              float* __restrict__ s_out, float* __restrict__ t_out) {
    int c = threadIdx.x;
    if (c >= C) return;
    float s = 0.f, q = 0.f;
    for (int r = 0; r < M; r++) {
        float v = A[(size_t)r*C + c];
        s += v; q += v*v;
    }
    float mean = s / (float)M;
    float var  = q / (float)M - mean*mean;
    float inv  = rsqrtf(var + EPSV);
    float sc   = g[c] * inv;
    s_out[c] = sc;
    t_out[c] = beta[c] - mean * sc;
}

// ---------------- apply bn + lrelu elementwise ----------------
__global__ void k_apply(const float* __restrict__ y, const float* __restrict__ s,
                        const float* __restrict__ t, float* __restrict__ h,
                        size_t total, int Cmask) {
    size_t i = (size_t)blockIdx.x * blockDim.x + threadIdx.x;
    if (i >= total) return;
    int c = (int)(i & (size_t)Cmask);
    h[i] = lrelu(s[c]*y[i] + t[c]);
}

// ---------------- knn per batch (validated) ----------------
__global__ void k_knn(const float* __restrict__ X, int C, int* __restrict__ nidx) {
    __shared__ float sX[64][68];
    __shared__ float sG[64][65];
    __shared__ float ssq[64];
    int tid = threadIdx.x;
    int tx = tid & 15, ty = tid >> 4;
    int b = blockIdx.x;
    float acc[4][4] = {};
    for (int c0 = 0; c0 < C; c0 += 64) {
        for (int i = tid; i < 64*64; i += 256) {
            int n = i >> 6, c = i & 63;
            sX[n][c] = X[(size_t)(b*64 + n)*C + c0 + c];
        }
        __syncthreads();
#pragma unroll 8
        for (int k = 0; k < 64; k++) {
            float a[4], bb[4];
#pragma unroll
            for (int i = 0; i < 4; i++) a[i]  = sX[ty*4 + i][k];
#pragma unroll
            for (int j = 0; j < 4; j++) bb[j] = sX[tx*4 + j][k];
#pragma unroll
            for (int i = 0; i < 4; i++)
#pragma unroll
                for (int j = 0; j < 4; j++) acc[i][j] += a[i]*bb[j];
        }
        __syncthreads();
    }
#pragma unroll
    for (int i = 0; i < 4; i++)
#pragma unroll
        for (int j = 0; j < 4; j++) sG[ty*4 + i][tx*4 + j] = acc[i][j];
    __syncthreads();
    if (tid < 64) ssq[tid] = sG[tid][tid];
    __syncthreads();
    if (tid < 64) {
        int n = tid;
        float sqn = ssq[n];
        float dist[17]; int mi[17]; int cnt = 0;
        for (int m = 0; m < 64; m++) {
            float dm = (sqn - 2.f*sG[n][m]) + ssq[m];
            if (cnt < 17) {
                int p = cnt;
                while (p > 0 && dist[p-1] > dm) { dist[p] = dist[p-1]; mi[p] = mi[p-1]; p--; }
                dist[p] = dm; mi[p] = m; cnt++;
            } else if (dm < dist[16]) {
                int p = 16;
                while (p > 0 && dist[p-1] > dm) { dist[p] = dist[p-1]; mi[p] = mi[p-1]; p--; }
                dist[p] = dm; mi[p] = m;
            }
        }
        for (int j = 0; j < 16; j++) nidx[(b*64 + n)*16 + j] = mi[j + 1];
    }
}

// ---------------- combine W_top/W_bot of layer-a weight ----------------
// Wc[:,0:C1] = W_bot (center coeff), Wc[:,C1:2C1] = W_top - W_bot (neighbor coeff)
// feat@W1 = xc@W_bot + xn@(W_top - W_bot) = Pc[center] + Pn[neighbor]
__global__ void k_prep_w(const float* __restrict__ W, float* __restrict__ Wc,
                         int C, int C1) {
    int i = blockIdx.x * blockDim.x + threadIdx.x;
    int tot = C * 2 * C1;
    if (i >= tot) return;
    int r = i / (2*C1), j = i % (2*C1);
    float v;
    if (j < C1) v = W[(size_t)(C + r)*C1 + j];
    else        v = W[(size_t)r*C1 + (j-C1)] - W[(size_t)(C + r)*C1 + (j-C1)];
    Wc[i] = v;
}

// ---------------- generic tiled GEMM 64x64x16 (validated) ----------------
__global__ void k_gemm(const float* __restrict__ A, const float* __restrict__ Bm,
                       float* __restrict__ Cout, int M, int Kd, int Nd) {
    __shared__ float sA[16][68];
    __shared__ float sB[16][64];
    int tid = threadIdx.x;
    int tx = tid & 15, ty = tid >> 4;
    int m0 = blockIdx.y * 64, n0 = blockIdx.x * 64;
    float acc[4][4] = {};
    for (int k0 = 0; k0 < Kd; k0 += 16) {
        for (int i = tid; i < 64*16; i += 256) {
            int m = i >> 4, k = i & 15;
            sA[k][m] = A[(size_t)(m0 + m)*Kd + k0 + k];
        }
        for (int i = tid; i < 16*64; i += 256) {
            int k = i >> 6, n = i & 63;
            sB[k][n] = Bm[(size_t)(k0 + k)*Nd + n0 + n];
        }
        __syncthreads();
#pragma unroll
        for (int k = 0; k < 16; k++) {
            float4 av = *(const float4*)&sA[k][ty*4];
            float4 bv = *(const float4*)&sB[k][tx*4];
            float a[4] = {av.x, av.y, av.z, av.w};
            float bb[4] = {bv.x, bv.y, bv.z, bv.w};
#pragma unroll
            for (int i = 0; i < 4; i++)
#pragma unroll
                for (int j = 0; j < 4; j++) acc[i][j] += a[i]*bb[j];
        }
        __syncthreads();
    }
#pragma unroll
    for (int i = 0; i < 4; i++) {
        float4 v = make_float4(acc[i][0], acc[i][1], acc[i][2], acc[i][3]);
        *(float4*)&Cout[(size_t)(m0 + ty*4 + i)*Nd + n0 + tx*4] = v;
    }
}

// ---------------- stats of gathered t = Pc[center] + Pn[neighbor] ----------------
__global__ void k_stats_t(const float* __restrict__ P, const int* __restrict__ nidx,
                          float* __restrict__ part, int C1) {
    int b = blockIdx.x;
    int c = threadIdx.x;   // threads == C1
    float s = 0.f, q = 0.f;
    for (int n = 0; n < 64; n++) {
        int pt = b*64 + n;
        float pcv = P[(size_t)pt*2*C1 + c];
        for (int k = 0; k < 16; k++) {
            int nb = nidx[pt*16 + k];
            float t = pcv + P[(size_t)(b*64 + nb)*2*C1 + C1 + c];
            s += t; q += t*t;
        }
    }
    part[(size_t)b*2*C1 + c]      = s;
    part[(size_t)b*2*C1 + C1 + c] = q;
}

// ---------------- fused: bn+lrelu(Pc+Pn) @ W2 + stats + scatter-max ----------------
// one block per (batch, 64-ch group); scatter target = neighbor idx (validated semantics);
// max over RAW outputs (bn∘lrelu∘max commute, positive scale); no H2 materialization.
__global__ void k_gemm2(const float* __restrict__ P, const float* __restrict__ W,
                        const int* __restrict__ nidx,
                        const float* __restrict__ sA_, const float* __restrict__ tA_,
                        unsigned* __restrict__ scat, float* __restrict__ part,
                        int C1, int C2) {
    __shared__ float sU[32][68];
    __shared__ float sW[32][64];
    __shared__ unsigned sS[64][64];
    __shared__ int sIdx[1024];
    int tid = threadIdx.x;
    int tx = tid & 15, ty = tid >> 4;
    int b = blockIdx.y;
    int cg = blockIdx.x * 64;
    for (int i = tid; i < 64*64; i += 256) sS[i >> 6][i & 63] = ENC_NEG;
    for (int i = tid; i < 1024; i += 256) sIdx[i] = nidx[b*1024 + i];
    float cs[4] = {0,0,0,0}, cq[4] = {0,0,0,0};
    __syncthreads();
    for (int rc = 0; rc < 16; rc++) {
        float acc[4][4] = {};
        for (int k0 = 0; k0 < C1; k0 += 32) {
            for (int i = tid; i < 32*64; i += 256) {
                int k = i >> 6, n = i & 63;
                sW[k][n] = W[(size_t)(k0 + k)*C2 + cg + n];
            }
            {
                int rr = tid >> 2;
                int kb = (tid & 3) * 8;
                int r  = rc*64 + rr;
                int n  = r >> 4;
                int kk = r & 15;
                int pt = b*64 + n;
                int nb = sIdx[n*16 + kk];
                const float* pc = P + (size_t)pt*2*C1 + k0 + kb;
                const float* pn = P + (size_t)(b*64 + nb)*2*C1 + C1 + k0 + kb;
#pragma unroll
                for (int j = 0; j < 8; j++) {
                    int c = k0 + kb + j;
                    float t = pc[j] + pn[j];
                    sU[kb + j][rr] = lrelu(sA_[c]*t + tA_[c]);
                }
            }
            __syncthreads();
#pragma unroll 8
            for (int k = 0; k < 32; k++) {
                float4 av = *(const float4*)&sU[k][ty*4];
                float4 bv = *(const float4*)&sW[k][tx*4];
                float a[4] = {av.x, av.y, av.z, av.w};
                float bb[4] = {bv.x, bv.y, bv.z, bv.w};
#pragma unroll
                for (int i = 0; i < 4; i++)
#pragma unroll
                    for (int j = 0; j < 4; j++) acc[i][j] += a[i]*bb[j];
            }
            __syncthreads();
        }
#pragma unroll
        for (int i = 0; i < 4; i++) {
            int r = rc*64 + ty*4 + i;
            int dst = sIdx[r];          // edge r -> neighbor index
#pragma unroll
            for (int j = 0; j < 4; j++) {
                float v = acc[i][j];
                cs[j] += v; cq[j] += v*v;
                atomicMax(&sS[dst][tx*4 + j], encf(v));
            }
        }
    }
    __syncthreads();
    for (int i = tid; i < 64*64; i += 256) {
        int n = i >> 6, c = i & 63;
        scat[(size_t)(b*64 + n)*C2 + cg + c] = sS[n][c];
    }
    // column reductions for bn stats (reuse sW)
    float* red = &sW[0][0];
#pragma unroll
    for (int j = 0; j < 4; j++) red[ty*64 + tx*4 + j] = cs[j];
    __syncthreads();
    if (tid < 64) {
        float s = 0.f;
        for (int y = 0; y < 16; y++) s += red[y*64 + tid];
        part[(size_t)b*2*C2 + cg + tid] = s;
    }
    __syncthreads();
#pragma unroll
    for (int j = 0; j < 4; j++) red[ty*64 + tx*4 + j] = cq[j];
    __syncthreads();
    if (tid < 64) {
        float s = 0.f;
        for (int y = 0; y < 16; y++) s += red[y*64 + tid];
        part[(size_t)b*2*C2 + C2 + cg + tid] = s;
    }
}

// ---------------- finish: bn+lrelu on pooled maxima, -inf -> 0 ----------------
__global__ void k_finish(const unsigned* __restrict__ scat, const float* __restrict__ s,
                         const float* __restrict__ t, float* __restrict__ h,
                         size_t total, int Cmask) {
    size_t i = (size_t)blockIdx.x * blockDim.x + threadIdx.x;
    if (i >= total) return;
    int c = (int)(i & (size_t)Cmask);
    unsigned u = scat[i];
    h[i] = (u == ENC_NEG) ? 0.f : lrelu(s[c]*decf(u) + t[c]);
}

// ---------------- global pooling ----------------
__global__ void k_pool(const float* __restrict__ h1, const float* __restrict__ h2,
                       const float* __restrict__ h3, float* __restrict__ pool) {
    int b = blockIdx.x;
    for (int c = threadIdx.x; c < 448; c += blockDim.x) {
        const float* src; int C, off;
        if (c < 64)       { src = h1; C = 64;  off = c; }
        else if (c < 192) { src = h2; C = 128; off = c - 64; }
        else              { src = h3; C = 256; off = c - 192; }
        float s = 0.f, mx = -CUDART_INF_F;
        for (int n = 0; n < 64; n++) {
            float v = src[(size_t)(b*64 + n)*C + off];
            s += v; mx = fmaxf(mx, v);
        }
        pool[b*896 + c]       = s * (1.f/64.f);
        pool[b*896 + 448 + c] = mx;
    }
}

// ---------------- classifier head ----------------
__global__ void k_head(const float* __restrict__ z, const float* __restrict__ w,
                       const float* __restrict__ bias, float* __restrict__ out) {
    int i = blockIdx.x * blockDim.x + threadIdx.x;
    if (i >= 1024) return;
    int r = i >> 1, c = i & 1;
    float s = 0.f;
    for (int k = 0; k < 256; k++) s += z[r*256 + k] * w[k*2 + c];
    out[i] = s + bias[c];
}

// ---------------- host orchestration: factored + fused edge conv ----------------
static void run_edge(const float* X, int C, int C1, int C2,
                     const float* wA, const float* gA, const float* bA,
                     const float* wB, const float* gB, const float* bB,
                     float* hout,
                     int* idxp, float* Pp, float* Wcp, float* partp,
                     unsigned* scatp, float* sAp, float* tAp, float* sBp, float* tBp) {
    k_knn<<<BB, 256>>>(X, C, idxp);
    int tot = C * 2 * C1;
    k_prep_w<<<(tot + 255)/256, 256>>>(wA, Wcp, C, C1);
    dim3 g1(2*C1/64, BN_/64);
    k_gemm<<<g1, 256>>>(X, Wcp, Pp, BN_, C, 2*C1);
    k_stats_t<<<BB, C1>>>(Pp, idxp, partp, C1);
    k_reduce_part<<<1, C1>>>(partp, BB, C1, gA, bA, sAp, tAp, 1.0f/(float)BNK);
    dim3 g2(C2/64, BB);
    k_gemm2<<<g2, 256>>>(Pp, wB, idxp, sAp, tAp, scatp, partp, C1, C2);
    k_reduce_part<<<1, C2>>>(partp, BB, C2, gB, bB, sBp, tBp, 1.0f/(float)BNK);
    k_finish<<<(unsigned)(((size_t)BN_*C2 + 255)/256), 256>>>(scatp, sBp, tBp, hout, (size_t)BN_*C2, C2 - 1);
}

extern "C" void kernel_launch(void* const* d_in, const int* in_sizes, int n_in,
                              void* d_out, int out_size) {
    const float *x, *w_in, *g_in, *b_in;
    const float *w1a, *g1a, *b1a, *w1b, *g1b, *b1b;
    const float *w2a, *g2a, *b2a, *w2b, *g2b, *b2b;
    const float *w3a, *g3a, *b3a, *w3b, *g3b, *b3b;
    const float *wc1, *gc1, *bc1, *wc2, *gc2, *bc2, *wc3, *bc3;

    bool alpha = (n_in == 31 && in_sizes[0] == 64 && in_sizes[7] == 32768 &&
                  in_sizes[27] == 458752 && in_sizes[30] == 196608);
    if (alpha) {
        b1a = (const float*)d_in[0];  b1b = (const float*)d_in[1];
        b2a = (const float*)d_in[2];  b2b = (const float*)d_in[3];
        b3a = (const float*)d_in[4];  b3b = (const float*)d_in[5];
        b_in = (const float*)d_in[6];
        bc1 = (const float*)d_in[8];  bc2 = (const float*)d_in[9];  bc3 = (const float*)d_in[10];
        g1a = (const float*)d_in[11]; g1b = (const float*)d_in[12];
        g2a = (const float*)d_in[13]; g2b = (const float*)d_in[14];
        g3a = (const float*)d_in[15]; g3b = (const float*)d_in[16];
        g_in = (const float*)d_in[17];
        gc1 = (const float*)d_in[18]; gc2 = (const float*)d_in[19];
        w1a = (const float*)d_in[20]; w1b = (const float*)d_in[21];
        w2a = (const float*)d_in[22]; w2b = (const float*)d_in[23];
        w3a = (const float*)d_in[24]; w3b = (const float*)d_in[25];
        w_in = (const float*)d_in[26];
        wc1 = (const float*)d_in[27]; wc2 = (const float*)d_in[28]; wc3 = (const float*)d_in[29];
        x   = (const float*)d_in[30];
    } else {
        x    = (const float*)d_in[0];
        w_in = (const float*)d_in[2];
        g_in = (const float*)d_in[3];  b_in = (const float*)d_in[4];
        w1a = (const float*)d_in[5];  g1a = (const float*)d_in[6];  b1a = (const float*)d_in[7];
        w1b = (const float*)d_in[8];  g1b = (const float*)d_in[9];  b1b = (const float*)d_in[10];
        w2a = (const float*)d_in[11]; g2a = (const float*)d_in[12]; b2a = (const float*)d_in[13];
        w2b = (const float*)d_in[14]; g2b = (const float*)d_in[15]; b2b = (const float*)d_in[16];
        w3a = (const float*)d_in[17]; g3a = (const float*)d_in[18]; b3a = (const float*)d_in[19];
        w3b = (const float*)d_in[20]; g3b = (const float*)d_in[21]; b3b = (const float*)d_in[22];
        wc1 = (const float*)d_in[23]; gc1 = (const float*)d_in[24]; bc1 = (const float*)d_in[25];
        wc2 = (const float*)d_in[26]; gc2 = (const float*)d_in[27]; bc2 = (const float*)d_in[28];
        wc3 = (const float*)d_in[29]; bc3 = (const float*)d_in[30];
    }
    float* out = (float*)d_out;

    float *h0, *h1, *h2, *h3, *P, *Wc, *y, *part, *sA, *tA, *sB, *tB, *pool, *z1p, *z1, *z2p, *z2;
    int* idxp;
    unsigned* scat;
    cudaGetSymbolAddress((void**)&h0,  d_h0);
    cudaGetSymbolAddress((void**)&h1,  d_h1);
    cudaGetSymbolAddress((void**)&h2,  d_h2);
    cudaGetSymbolAddress((void**)&h3,  d_h3);
    cudaGetSymbolAddress((void**)&idxp, d_idx);
    cudaGetSymbolAddress((void**)&P,   d_P);
    cudaGetSymbolAddress((void**)&Wc,  d_Wc);
    cudaGetSymbolAddress((void**)&y,   d_y);
    cudaGetSymbolAddress((void**)&scat, d_scat);
    cudaGetSymbolAddress((void**)&part, d_part);
    cudaGetSymbolAddress((void**)&sA,  d_sA);
    cudaGetSymbolAddress((void**)&tA,  d_tA);
    cudaGetSymbolAddress((void**)&sB,  d_sB);
    cudaGetSymbolAddress((void**)&tB,  d_tB);
    cudaGetSymbolAddress((void**)&pool, d_pool);
    cudaGetSymbolAddress((void**)&z1p, d_z1p);
    cudaGetSymbolAddress((void**)&z1,  d_z1);
    cudaGetSymbolAddress((void**)&z2p, d_z2p);
    cudaGetSymbolAddress((void**)&z2,  d_z2);

    // ---- input layer: h0 = lrelu(bn(x @ w_in)) ----
    k_ingemm<<<BN_/4, 256>>>(x, w_in, y);
    k_statp<<<128, 64>>>(y, part, 64, 256);
    k_reduce_part<<<1, 64>>>(part, 128, 64, g_in, b_in, sA, tA, 1.0f/(float)BN_);
    k_apply<<<(BN_*64 + 255)/256, 256>>>(y, sA, tA, h0, (size_t)BN_*64, 63);

    // ---- edge convs (factored + fused) ----
    run_edge(h0, 64, 64, 64,   w1a, g1a, b1a, w1b, g1b, b1b, h1, idxp, P, Wc, part, scat, sA, tA, sB, tB);
    run_edge(h1, 64, 128, 128, w2a, g2a, b2a, w2b, g2b, b2b, h2, idxp, P, Wc, part, scat, sA, tA, sB, tB);
    run_edge(h2, 128, 256, 256, w3a, g3a, b3a, w3b, g3b, b3b, h3, idxp, P, Wc, part, scat, sA, tA, sB, tB);

    // ---- pooling ----
    k_pool<<<BB, 256>>>(h1, h2, h3, pool);

    // ---- classifier ----
    {
        dim3 g(512/64, BB/64);
        k_gemm<<<g, 256>>>(pool, wc1, z1p, BB, 896, 512);
        k_bnstat_rows<<<1, 512>>>(z1p, BB, 512, gc1, bc1, sA, tA);
        k_apply<<<(BB*512 + 255)/256, 256>>>(z1p, sA, tA, z1, (size_t)BB*512, 511);
    }
    {
        dim3 g(256/64, BB/64);
        k_gemm<<<g, 256>>>(z1, wc2, z2p, BB, 512, 256);
        k_bnstat_rows<<<1, 256>>>(z2p, BB, 256, gc2, bc2, sA, tA);
        k_apply<<<(BB*256 + 255)/256, 256>>>(z2p, sA, tA, z2, (size_t)BB*256, 255);
    }
    k_head<<<4, 256>>>(z2, wc3, bc3, out);
}